// round 8
// baseline (speedup 1.0000x reference)
#include <cuda_runtime.h>
#include <mma.h>
#include <math.h>

using namespace nvcuda;

#define HEADS 16
#define DIM 64
#define NTOK 2048
#define CHID 1024
#define BATCH 2
#define SCALE 0.125f

__device__ float g_qkv[3UL * BATCH * HEADS * NTOK * DIM];

typedef wmma::fragment<wmma::matrix_a, 16, 16, 8, wmma::precision::tf32, wmma::row_major> AFrag;
typedef wmma::fragment<wmma::matrix_b, 16, 16, 8, wmma::precision::tf32, wmma::col_major> BFragCol;
typedef wmma::fragment<wmma::matrix_b, 16, 16, 8, wmma::precision::tf32, wmma::row_major> BFragRow;
typedef wmma::fragment<wmma::accumulator, 16, 16, 8, float> CFrag;

__device__ __forceinline__ float tf32r(float x) { return wmma::__float_to_tf32(x); }
__device__ __forceinline__ float4 tf4(float4 v) {
    v.x = tf32r(v.x); v.y = tf32r(v.y); v.z = tf32r(v.z); v.w = tf32r(v.w);
    return v;
}
__device__ __forceinline__ void cp16(void* s, const void* g) {
    unsigned sa = (unsigned)__cvta_generic_to_shared(s);
    asm volatile("cp.async.cg.shared.global [%0], [%1], 16;" :: "r"(sa), "l"(g));
}
#define CP_COMMIT() asm volatile("cp.async.commit_group;")
#define CP_WAIT(n) asm volatile("cp.async.wait_group %0;" :: "n"(n))

// ---------------- QKV projection GEMM (tf32, cp.async double-buffered) ----------------
__global__ __launch_bounds__(256) void qkv_gemm(const float* __restrict__ X,
                                                const float* __restrict__ Wt) {
    extern __shared__ float sm1[];
    float* As = sm1;                  // [2][128*24]
    float* Bs = sm1 + 2 * 128 * 24;   // [2][128*24]
    float* Cs = sm1;                  // epilogue alias [128][72]

    int t = threadIdx.x;
    int bm = blockIdx.y, bn = blockIdx.x;
    int w = t >> 5;
    int wr = w >> 1, wc = w & 1;
    int lrow = t >> 1;
    int lq = (t & 1) * 8;

    const float* Ag = X + (size_t)(bm * 128 + lrow) * 1024 + lq;
    const float* Bg = Wt + (size_t)(bn * 128 + lrow) * 1024 + lq;

    CFrag acc[2][4];
#pragma unroll
    for (int i = 0; i < 2; i++)
#pragma unroll
        for (int j = 0; j < 4; j++) wmma::fill_fragment(acc[i][j], 0.f);

    // prefetch slab 0
    {
        float* ad = &As[lrow * 24 + lq];
        float* bd = &Bs[lrow * 24 + lq];
        cp16(ad, Ag); cp16(ad + 4, Ag + 4);
        cp16(bd, Bg); cp16(bd + 4, Bg + 4);
        CP_COMMIT();
    }

    int buf = 0;
    for (int k0 = 0; k0 < 1024; k0 += 16, buf ^= 1) {
        if (k0 + 16 < 1024) {
            float* ad = &As[(buf ^ 1) * (128 * 24) + lrow * 24 + lq];
            float* bd = &Bs[(buf ^ 1) * (128 * 24) + lrow * 24 + lq];
            cp16(ad, Ag + k0 + 16); cp16(ad + 4, Ag + k0 + 20);
            cp16(bd, Bg + k0 + 16); cp16(bd + 4, Bg + k0 + 20);
            CP_COMMIT();
            CP_WAIT(1);
        } else {
            CP_WAIT(0);
        }
        __syncthreads();
        float* A = As + buf * (128 * 24);
        float* B = Bs + buf * (128 * 24);
#pragma unroll
        for (int ks = 0; ks < 2; ks++) {
            AFrag af[2];
            BFragCol bf[4];
#pragma unroll
            for (int i = 0; i < 2; i++) {
                wmma::load_matrix_sync(af[i], &A[(wr * 32 + i * 16) * 24 + ks * 8], 24);
#pragma unroll
                for (int e = 0; e < af[i].num_elements; e++) af[i].x[e] = tf32r(af[i].x[e]);
            }
#pragma unroll
            for (int j = 0; j < 4; j++) {
                wmma::load_matrix_sync(bf[j], &B[(wc * 64 + j * 16) * 24 + ks * 8], 24);
#pragma unroll
                for (int e = 0; e < bf[j].num_elements; e++) bf[j].x[e] = tf32r(bf[j].x[e]);
            }
#pragma unroll
            for (int i = 0; i < 2; i++)
#pragma unroll
                for (int j = 0; j < 4; j++)
                    wmma::mma_sync(acc[i][j], af[i], bf[j], acc[i][j]);
        }
        __syncthreads();
    }

    // epilogue: round to tf32, scatter to g_qkv layout
#pragma unroll
    for (int hf = 0; hf < 2; hf++) {
        if (wc == hf) {
#pragma unroll
            for (int i = 0; i < 2; i++)
#pragma unroll
                for (int j = 0; j < 4; j++)
                    wmma::store_matrix_sync(&Cs[(wr * 32 + i * 16) * 72 + j * 16],
                                            acc[i][j], 72, wmma::mem_row_major);
        }
        __syncthreads();
        int colbase = bn * 128 + hf * 64;
        int qkv = colbase >> 10;
        int hh = (colbase >> 6) & 15;
#pragma unroll
        for (int i = 0; i < 8; i++) {
            int fi = t + (i << 8);
            int row = fi >> 4;
            int c4 = fi & 15;
            int m = bm * 128 + row;
            int b = m >> 11, n = m & 2047;
            float4 v = tf4(*(const float4*)&Cs[row * 72 + c4 * 4]);
            float* dst = g_qkv + ((((size_t)qkv * BATCH + b) * HEADS + hh) * NTOK + n) * DIM + c4 * 4;
            *(float4*)dst = v;
        }
        __syncthreads();
    }
}

// ---------------- attention: 128-row Q tiles, flash-style (no max) ----------------
__global__ __launch_bounds__(256) void attn_scores(const void* __restrict__ mask_raw,
                                                   float* __restrict__ att_out,
                                                   float* __restrict__ w_out) {
    extern __shared__ float sm[];
    float* qs = sm;                     // [128][72]
    float* kb = qs + 128 * 72;          // 2 x [128][72]
    float* sc = kb + 2 * 128 * 72;      // [128][132]
    float* rowsum = sc + 128 * 132;     // [128]  (becomes 1/rowsum after Phase A)
    unsigned char* mj = (unsigned char*)(rowsum + 128);  // 2048
    unsigned char* mr = mj + 2048;      // 128

    __shared__ int s_is32;

    int t = threadIdx.x;
    int w = t >> 5;
    int b = blockIdx.z, h = blockIdx.y;
    int row0 = blockIdx.x << 7;

    const float* Qg = g_qkv + (((size_t)(0 * BATCH + b) * HEADS + h) * NTOK + row0) * DIM;
    const float* Kg = g_qkv + (((size_t)(1 * BATCH + b) * HEADS + h) * NTOK) * DIM;
    const float* Vg = g_qkv + (((size_t)(2 * BATCH + b) * HEADS + h) * NTOK) * DIM;
    float* Wt = w_out + ((size_t)(b * HEADS + h) * NTOK + row0) * NTOK;

    // stage Q + K chunk 0
#pragma unroll
    for (int i = 0; i < 8; i++) {
        int fi = t + (i << 8);
        int r = fi >> 4;
        int d4 = (fi & 15) << 2;
        cp16(&qs[r * 72 + d4], Qg + (size_t)r * DIM + d4);
        cp16(&kb[r * 72 + d4], Kg + (size_t)r * DIM + d4);
    }
    CP_COMMIT();

    if (t == 0) {
        const unsigned int* mw = (const unsigned int*)mask_raw;
        int is32 = 1;
        for (int i = 0; i < 64; i++)
            if (mw[i] > 1u) { is32 = 0; break; }
        s_is32 = is32;
    }
    __syncthreads();
    {
        const int is32 = s_is32;
        const int* m32 = (const int*)mask_raw;
        const unsigned char* m8 = (const unsigned char*)mask_raw;
#pragma unroll
        for (int i = 0; i < 8; i++) {
            int j = t + (i << 8);
            mj[j] = is32 ? (unsigned char)(m32[(size_t)b * NTOK + j] != 0)
                         : m8[(size_t)b * NTOK + j];
        }
        // row mask direct from global (reading mj here would race)
        if (t < 128) {
            int idx = b * NTOK + row0 + t;
            int mv = is32 ? (m32[idx] != 0) : (m8[idx] != 0);
            mr[t] = (unsigned char)mv;
            rowsum[t] = 0.f;
        }
    }
    __syncthreads();

    // ---------- Phase A: e = masked exp(QK^T * SCALE) -> w_out (unnormalized) + rowsum ----------
    {
        AFrag aq[8];

        for (int cb = 0; cb < 16; cb++) {
            if (cb + 1 < 16) {
                float* dst = kb + ((cb + 1) & 1) * (128 * 72);
#pragma unroll
                for (int i = 0; i < 8; i++) {
                    int fi = t + (i << 8);
                    int r = fi >> 4;
                    int d4 = (fi & 15) << 2;
                    cp16(&dst[r * 72 + d4], Kg + (size_t)((cb + 1) * 128 + r) * DIM + d4);
                }
                CP_COMMIT();
                CP_WAIT(1);
            } else {
                CP_WAIT(0);
            }
            __syncthreads();
            float* buf = kb + (cb & 1) * (128 * 72);

            if (cb == 0) {
#pragma unroll
                for (int k = 0; k < 8; k++)
                    wmma::load_matrix_sync(aq[k], &qs[(w * 16) * 72 + k * 8], 72);
            }

#pragma unroll
            for (int c = 0; c < 8; c++) {
                CFrag acc;
                wmma::fill_fragment(acc, 0.f);
#pragma unroll
                for (int k = 0; k < 8; k++) {
                    BFragCol bf;
                    wmma::load_matrix_sync(bf, &buf[(c * 16) * 72 + k * 8], 72);
                    wmma::mma_sync(acc, aq[k], bf, acc);
                }
                wmma::store_matrix_sync(&sc[(w * 16) * 132 + c * 16], acc, 132, wmma::mem_row_major);
            }
            __syncthreads();

            {
                int r = t >> 1;
                int c0 = (t & 1) << 6;
                bool rm = mr[r] != 0;
                const unsigned char* mjc = mj + cb * 128 + c0;
                float* p = &sc[r * 132 + c0];
                float lsum = 0.f;
#pragma unroll
                for (int j4 = 0; j4 < 16; j4++) {
                    float4 v = *(const float4*)(p + j4 * 4);
                    float4 e;
                    e.x = rm ? 1.f : (mjc[j4 * 4 + 0] ? 0.f : __expf(v.x * SCALE));
                    e.y = rm ? 1.f : (mjc[j4 * 4 + 1] ? 0.f : __expf(v.y * SCALE));
                    e.z = rm ? 1.f : (mjc[j4 * 4 + 2] ? 0.f : __expf(v.z * SCALE));
                    e.w = rm ? 1.f : (mjc[j4 * 4 + 3] ? 0.f : __expf(v.w * SCALE));
                    *(float4*)(p + j4 * 4) = e;
                    lsum += e.x + e.y + e.z + e.w;
                }
                float osum = __shfl_xor_sync(0xffffffffu, lsum, 1);
                if ((t & 1) == 0) rowsum[r] += lsum + osum;
            }
            __syncthreads();

#pragma unroll
            for (int i = 0; i < 16; i++) {
                int fi = t + (i << 8);
                int r = fi >> 5;
                int c4 = (fi & 31) << 2;
                *(float4*)(Wt + (size_t)r * NTOK + cb * 128 + c4) = *(const float4*)&sc[r * 132 + c4];
            }
            __syncthreads();
        }
    }

    // rowsum -> 1/rowsum
    if (t < 128) rowsum[t] = 1.f / rowsum[t];
    __syncthreads();

    // ---------- Phase B: normalize weights in-place + att = w @ V ----------
    {
        CFrag acc[4];
#pragma unroll
        for (int dt = 0; dt < 4; dt++) wmma::fill_fragment(acc[dt], 0.f);

#pragma unroll
        for (int i = 0; i < 8; i++) {
            int fi = t + (i << 8);
            int r = fi >> 4;
            int d4 = (fi & 15) << 2;
            cp16(&kb[r * 72 + d4], Vg + (size_t)r * DIM + d4);
        }
        CP_COMMIT();

        for (int cb = 0; cb < 16; cb++) {
            // reload e chunk, normalize, write final weights, stage for MMA
#pragma unroll
            for (int i = 0; i < 16; i++) {
                int fi = t + (i << 8);
                int r = fi >> 5;
                int c4 = (fi & 31) << 2;
                float inv = rowsum[r];
                float4 v = *(const float4*)(Wt + (size_t)r * NTOK + cb * 128 + c4);
                v.x *= inv; v.y *= inv; v.z *= inv; v.w *= inv;
                *(float4*)(Wt + (size_t)r * NTOK + cb * 128 + c4) = v;   // final normalized weights
                *(float4*)&sc[r * 132 + c4] = v;
            }
            if (cb + 1 < 16) {
                float* dst = kb + ((cb + 1) & 1) * (128 * 72);
#pragma unroll
                for (int i = 0; i < 8; i++) {
                    int fi = t + (i << 8);
                    int r = fi >> 4;
                    int d4 = (fi & 15) << 2;
                    cp16(&dst[r * 72 + d4], Vg + (size_t)((cb + 1) * 128 + r) * DIM + d4);
                }
                CP_COMMIT();
                CP_WAIT(1);
            } else {
                CP_WAIT(0);
            }
            __syncthreads();
            float* buf = kb + (cb & 1) * (128 * 72);

#pragma unroll
            for (int k = 0; k < 16; k++) {
                AFrag ae;
                wmma::load_matrix_sync(ae, &sc[(w * 16) * 132 + k * 8], 132);
#pragma unroll
                for (int e = 0; e < ae.num_elements; e++) ae.x[e] = tf32r(ae.x[e]);
#pragma unroll
                for (int dt = 0; dt < 4; dt++) {
                    BFragRow bv;   // V already tf32-valued
                    wmma::load_matrix_sync(bv, &buf[(k * 8) * 72 + dt * 16], 72);
                    wmma::mma_sync(acc[dt], ae, bv, acc[dt]);
                }
            }
            __syncthreads();
        }

#pragma unroll
        for (int dt = 0; dt < 4; dt++)
            wmma::store_matrix_sync(&sc[(w * 16) * 132 + dt * 16], acc[dt], 132, wmma::mem_row_major);
        __syncthreads();
        {
            int r = t >> 1;
            int d0 = (t & 1) << 5;
            float* dst = att_out + ((size_t)b * NTOK + row0 + r) * CHID + h * DIM + d0;
#pragma unroll
            for (int j4 = 0; j4 < 8; j4++)
                *(float4*)(dst + j4 * 4) = *(const float4*)&sc[r * 132 + d0 + j4 * 4];
        }
    }
}

#define GEMM_SMEM (2 * 2 * 128 * 24 * 4)
#define ATT_SMEM ((128 * 72 + 2 * 128 * 72 + 128 * 132 + 128) * 4 + 2048 + 128)

extern "C" void kernel_launch(void* const* d_in, const int* in_sizes, int n_in,
                              void* d_out, int out_size) {
    (void)in_sizes; (void)n_in; (void)out_size;
    const float* X = (const float*)d_in[0];
    const float* W = (const float*)d_in[1];
    const void* mask = d_in[2];
    float* att = (float*)d_out;
    float* wts = (float*)d_out + (size_t)BATCH * NTOK * CHID;

    cudaFuncSetAttribute(attn_scores, cudaFuncAttributeMaxDynamicSharedMemorySize, ATT_SMEM);

    qkv_gemm<<<dim3(24, 32), 256, GEMM_SMEM>>>(X, W);
    attn_scores<<<dim3(16, HEADS, BATCH), 256, ATT_SMEM>>>(mask, att, wts);
}

// round 9
// speedup vs baseline: 1.3450x; 1.3450x over previous
#include <cuda_runtime.h>
#include <mma.h>
#include <math.h>

using namespace nvcuda;

#define HEADS 16
#define DIM 64
#define NTOK 2048
#define CHID 1024
#define BATCH 2
#define SCALE 0.125f

__device__ float g_qkv[3UL * BATCH * HEADS * NTOK * DIM];
__device__ float g_inv[(size_t)BATCH * HEADS * NTOK];

typedef wmma::fragment<wmma::matrix_a, 16, 16, 8, wmma::precision::tf32, wmma::row_major> AFrag;
typedef wmma::fragment<wmma::matrix_b, 16, 16, 8, wmma::precision::tf32, wmma::col_major> BFragCol;
typedef wmma::fragment<wmma::matrix_b, 16, 16, 8, wmma::precision::tf32, wmma::row_major> BFragRow;
typedef wmma::fragment<wmma::accumulator, 16, 16, 8, float> CFrag;

__device__ __forceinline__ float tf32r(float x) { return wmma::__float_to_tf32(x); }
__device__ __forceinline__ float4 tf4(float4 v) {
    v.x = tf32r(v.x); v.y = tf32r(v.y); v.z = tf32r(v.z); v.w = tf32r(v.w);
    return v;
}
__device__ __forceinline__ void cp16(void* s, const void* g) {
    unsigned sa = (unsigned)__cvta_generic_to_shared(s);
    asm volatile("cp.async.cg.shared.global [%0], [%1], 16;" :: "r"(sa), "l"(g));
}
#define CP_COMMIT() asm volatile("cp.async.commit_group;")
#define CP_WAIT(n) asm volatile("cp.async.wait_group %0;" :: "n"(n))

// ---------------- QKV projection GEMM (R7 version, measured 438us) ----------------
__global__ __launch_bounds__(256) void qkv_gemm(const float* __restrict__ X,
                                                const float* __restrict__ Wt) {
    extern __shared__ float sm1[];
    float* As = sm1;
    float* Bs = sm1 + 128 * 24;
    float* Cs = sm1;

    int t = threadIdx.x;
    int bm = blockIdx.y, bn = blockIdx.x;
    int w = t >> 5;
    int wr = w >> 1, wc = w & 1;
    int lrow = t >> 1;
    int lq = (t & 1) * 8;

    const float* Ag = X + (size_t)(bm * 128 + lrow) * 1024 + lq;
    const float* Bg = Wt + (size_t)(bn * 128 + lrow) * 1024 + lq;

    CFrag acc[2][4];
#pragma unroll
    for (int i = 0; i < 2; i++)
#pragma unroll
        for (int j = 0; j < 4; j++) wmma::fill_fragment(acc[i][j], 0.f);

    float4 a0 = *(const float4*)(Ag);
    float4 a1 = *(const float4*)(Ag + 4);
    float4 b0 = *(const float4*)(Bg);
    float4 b1 = *(const float4*)(Bg + 4);

    for (int k0 = 0; k0 < 1024; k0 += 16) {
        float* ap = &As[lrow * 24 + lq];
        float* bp = &Bs[lrow * 24 + lq];
        *(float4*)ap = tf4(a0);
        *(float4*)(ap + 4) = tf4(a1);
        *(float4*)bp = tf4(b0);
        *(float4*)(bp + 4) = tf4(b1);
        __syncthreads();
        if (k0 + 16 < 1024) {
            a0 = *(const float4*)(Ag + k0 + 16);
            a1 = *(const float4*)(Ag + k0 + 20);
            b0 = *(const float4*)(Bg + k0 + 16);
            b1 = *(const float4*)(Bg + k0 + 20);
        }
#pragma unroll
        for (int ks = 0; ks < 2; ks++) {
            AFrag af[2];
            BFragCol bf[4];
#pragma unroll
            for (int i = 0; i < 2; i++)
                wmma::load_matrix_sync(af[i], &As[(wr * 32 + i * 16) * 24 + ks * 8], 24);
#pragma unroll
            for (int j = 0; j < 4; j++)
                wmma::load_matrix_sync(bf[j], &Bs[(wc * 64 + j * 16) * 24 + ks * 8], 24);
#pragma unroll
            for (int i = 0; i < 2; i++)
#pragma unroll
                for (int j = 0; j < 4; j++)
                    wmma::mma_sync(acc[i][j], af[i], bf[j], acc[i][j]);
        }
        __syncthreads();
    }

#pragma unroll
    for (int hf = 0; hf < 2; hf++) {
        if (wc == hf) {
#pragma unroll
            for (int i = 0; i < 2; i++)
#pragma unroll
                for (int j = 0; j < 4; j++)
                    wmma::store_matrix_sync(&Cs[(wr * 32 + i * 16) * 72 + j * 16],
                                            acc[i][j], 72, wmma::mem_row_major);
        }
        __syncthreads();
        int colbase = bn * 128 + hf * 64;
        int qkv = colbase >> 10;
        int hh = (colbase >> 6) & 15;
#pragma unroll
        for (int i = 0; i < 8; i++) {
            int fi = t + (i << 8);
            int row = fi >> 4;
            int c4 = fi & 15;
            int m = bm * 128 + row;
            int b = m >> 11, n = m & 2047;
            float4 v = tf4(*(const float4*)&Cs[row * 72 + c4 * 4]);
            float* dst = g_qkv + ((((size_t)qkv * BATCH + b) * HEADS + hh) * NTOK + n) * DIM + c4 * 4;
            *(float4*)dst = v;
        }
        __syncthreads();
    }
}

// ---------------- attention: 64-row Q tiles, 64-col chunks, high occupancy ----------------
__global__ __launch_bounds__(256, 2) void attn_scores(const void* __restrict__ mask_raw,
                                                      float* __restrict__ att_out,
                                                      float* __restrict__ w_out) {
    extern __shared__ float sm[];
    float* qs = sm;                     // [64][72]
    float* kb = qs + 64 * 72;           // 2 x [64][72]
    float* sc = kb + 2 * 64 * 72;       // [64][68]
    float* rowsum = sc + 64 * 68;       // [64]
    unsigned char* mj = (unsigned char*)(rowsum + 64);  // 2048
    unsigned char* mr = mj + 2048;      // 64

    __shared__ int s_is32;

    int t = threadIdx.x;
    int w = t >> 5;
    int wr = w >> 1;      // row group (16 rows)
    int wh = w & 1;       // col/d half (32)
    int b = blockIdx.z, h = blockIdx.y;
    int row0 = blockIdx.x << 6;

    const float* Qg = g_qkv + (((size_t)(0 * BATCH + b) * HEADS + h) * NTOK + row0) * DIM;
    const float* Kg = g_qkv + (((size_t)(1 * BATCH + b) * HEADS + h) * NTOK) * DIM;
    const float* Vg = g_qkv + (((size_t)(2 * BATCH + b) * HEADS + h) * NTOK) * DIM;
    float* Wt = w_out + ((size_t)(b * HEADS + h) * NTOK + row0) * NTOK;

    // stage Q tile + K chunk 0 (64 rows x 64 floats = 1024 f4 each; 4/thread)
#pragma unroll
    for (int i = 0; i < 4; i++) {
        int fi = t + (i << 8);
        int r = fi >> 4;
        int d4 = (fi & 15) << 2;
        cp16(&qs[r * 72 + d4], Qg + (size_t)r * DIM + d4);
        cp16(&kb[r * 72 + d4], Kg + (size_t)r * DIM + d4);
    }
    CP_COMMIT();

    if (t == 0) {
        const unsigned int* mw = (const unsigned int*)mask_raw;
        int is32 = 1;
        for (int i = 0; i < 64; i++)
            if (mw[i] > 1u) { is32 = 0; break; }
        s_is32 = is32;
    }
    __syncthreads();
    {
        const int is32 = s_is32;
        const int* m32 = (const int*)mask_raw;
        const unsigned char* m8 = (const unsigned char*)mask_raw;
#pragma unroll
        for (int i = 0; i < 8; i++) {
            int j = t + (i << 8);
            mj[j] = is32 ? (unsigned char)(m32[(size_t)b * NTOK + j] != 0)
                         : m8[(size_t)b * NTOK + j];
        }
        // row mask direct from global (reading mj here would race)
        if (t < 64) {
            int idx = b * NTOK + row0 + t;
            int mv = is32 ? (m32[idx] != 0) : (m8[idx] != 0);
            mr[t] = (unsigned char)mv;
            rowsum[t] = 0.f;
        }
    }
    __syncthreads();

    // ---------- Phase A: e = masked exp(QK^T*SCALE) -> w_out (unnormalized) + rowsum ----------
    {
        AFrag aq[8];

        for (int cb = 0; cb < 32; cb++) {
            if (cb + 1 < 32) {
                float* dst = kb + ((cb + 1) & 1) * (64 * 72);
#pragma unroll
                for (int i = 0; i < 4; i++) {
                    int fi = t + (i << 8);
                    int r = fi >> 4;
                    int d4 = (fi & 15) << 2;
                    cp16(&dst[r * 72 + d4], Kg + (size_t)((cb + 1) * 64 + r) * DIM + d4);
                }
                CP_COMMIT();
                CP_WAIT(1);
            } else {
                CP_WAIT(0);
            }
            __syncthreads();
            float* buf = kb + (cb & 1) * (64 * 72);

            if (cb == 0) {
#pragma unroll
                for (int k = 0; k < 8; k++)
                    wmma::load_matrix_sync(aq[k], &qs[(wr * 16) * 72 + k * 8], 72);
            }

            // warp computes 16 rows x 32 cols of S
#pragma unroll
            for (int c = 0; c < 2; c++) {
                CFrag acc;
                wmma::fill_fragment(acc, 0.f);
#pragma unroll
                for (int k = 0; k < 8; k++) {
                    BFragCol bf;
                    wmma::load_matrix_sync(bf, &buf[(wh * 32 + c * 16) * 72 + k * 8], 72);
                    wmma::mma_sync(acc, aq[k], bf, acc);
                }
                wmma::store_matrix_sync(&sc[(wr * 16) * 68 + wh * 32 + c * 16], acc, 68,
                                        wmma::mem_row_major);
            }
            __syncthreads();

            // e = masked exp; accumulate rowsum (4 threads per row)
            {
                int r = t >> 2;
                int c0 = (t & 3) << 4;
                bool rm = mr[r] != 0;
                const unsigned char* mjc = mj + cb * 64 + c0;
                float* p = &sc[r * 68 + c0];
                float lsum = 0.f;
#pragma unroll
                for (int j4 = 0; j4 < 4; j4++) {
                    float4 v = *(const float4*)(p + j4 * 4);
                    float4 e;
                    e.x = rm ? 1.f : (mjc[j4 * 4 + 0] ? 0.f : __expf(v.x * SCALE));
                    e.y = rm ? 1.f : (mjc[j4 * 4 + 1] ? 0.f : __expf(v.y * SCALE));
                    e.z = rm ? 1.f : (mjc[j4 * 4 + 2] ? 0.f : __expf(v.z * SCALE));
                    e.w = rm ? 1.f : (mjc[j4 * 4 + 3] ? 0.f : __expf(v.w * SCALE));
                    *(float4*)(p + j4 * 4) = e;
                    lsum += e.x + e.y + e.z + e.w;
                }
                lsum += __shfl_xor_sync(0xffffffffu, lsum, 1);
                lsum += __shfl_xor_sync(0xffffffffu, lsum, 2);
                if ((t & 3) == 0) rowsum[r] += lsum;
            }
            __syncthreads();

            // store e chunk (64 rows x 16 f4 = 1024 f4; 4/thread)
#pragma unroll
            for (int i = 0; i < 4; i++) {
                int fi = t + (i << 8);
                int r = fi >> 4;
                int c4 = (fi & 15) << 2;
                *(float4*)(Wt + (size_t)r * NTOK + cb * 64 + c4) = *(const float4*)&sc[r * 68 + c4];
            }
            // next iteration's post-wait __syncthreads orders these reads vs new MMA stores
        }
    }

    __syncthreads();
    if (t < 64) {
        float inv = 1.f / rowsum[t];
        rowsum[t] = inv;
        g_inv[((size_t)(b * HEADS + h) * NTOK) + row0 + t] = inv;
    }
    __syncthreads();

    // ---------- Phase B: att = (e @ V) * inv ----------
    {
        CFrag acc[2];
#pragma unroll
        for (int dt = 0; dt < 2; dt++) wmma::fill_fragment(acc[dt], 0.f);

        // prefetch V chunk 0
#pragma unroll
        for (int i = 0; i < 4; i++) {
            int fi = t + (i << 8);
            int r = fi >> 4;
            int d4 = (fi & 15) << 2;
            cp16(&kb[r * 72 + d4], Vg + (size_t)r * DIM + d4);
        }
        CP_COMMIT();

        for (int cb = 0; cb < 32; cb++) {
            // reload e chunk (LDG -> tf32 round -> STS)
#pragma unroll
            for (int i = 0; i < 4; i++) {
                int fi = t + (i << 8);
                int r = fi >> 4;
                int c4 = (fi & 15) << 2;
                float4 v = *(const float4*)(Wt + (size_t)r * NTOK + cb * 64 + c4);
                *(float4*)&sc[r * 68 + c4] = tf4(v);
            }
            if (cb + 1 < 32) {
                float* dst = kb + ((cb + 1) & 1) * (64 * 72);
#pragma unroll
                for (int i = 0; i < 4; i++) {
                    int fi = t + (i << 8);
                    int r = fi >> 4;
                    int d4 = (fi & 15) << 2;
                    cp16(&dst[r * 72 + d4], Vg + (size_t)((cb + 1) * 64 + r) * DIM + d4);
                }
                CP_COMMIT();
                CP_WAIT(1);
            } else {
                CP_WAIT(0);
            }
            __syncthreads();
            float* buf = kb + (cb & 1) * (64 * 72);

            // warp: 16 rows x 32 d-cols, full 64-k chunk
#pragma unroll
            for (int k = 0; k < 8; k++) {
                AFrag ae;
                wmma::load_matrix_sync(ae, &sc[(wr * 16) * 68 + k * 8], 68);
#pragma unroll
                for (int dt = 0; dt < 2; dt++) {
                    BFragRow bv;
                    wmma::load_matrix_sync(bv, &buf[(k * 8) * 72 + wh * 32 + dt * 16], 72);
                    wmma::mma_sync(acc[dt], ae, bv, acc[dt]);
                }
            }
            __syncthreads();
        }

        // stage result, normalize, write att
#pragma unroll
        for (int dt = 0; dt < 2; dt++)
            wmma::store_matrix_sync(&sc[(wr * 16) * 68 + wh * 32 + dt * 16], acc[dt], 68,
                                    wmma::mem_row_major);
        __syncthreads();
        {
            int r = t >> 2;
            int d0 = (t & 3) << 4;
            float inv = rowsum[r];
            float* dst = att_out + ((size_t)b * NTOK + row0 + r) * CHID + h * DIM + d0;
#pragma unroll
            for (int j4 = 0; j4 < 4; j4++) {
                float4 v = *(const float4*)&sc[r * 68 + d0 + j4 * 4];
                v.x *= inv; v.y *= inv; v.z *= inv; v.w *= inv;
                *(float4*)(dst + j4 * 4) = v;
            }
        }
    }
}

// ---------------- normalize weights (full-chip parallel) ----------------
__global__ __launch_bounds__(256) void normalize_w(float* __restrict__ w_out) {
    size_t nf4 = (size_t)BATCH * HEADS * NTOK * NTOK / 4;
    size_t stride = (size_t)gridDim.x * blockDim.x;
    for (size_t i = (size_t)blockIdx.x * blockDim.x + threadIdx.x; i < nf4; i += stride) {
        size_t fidx = i << 2;
        float inv = __ldg(&g_inv[fidx >> 11]);
        float4 v = *(float4*)(w_out + fidx);
        v.x *= inv; v.y *= inv; v.z *= inv; v.w *= inv;
        *(float4*)(w_out + fidx) = v;
    }
}

#define GEMM_SMEM (128 * 72 * 4)
#define ATT_SMEM ((64 * 72 + 2 * 64 * 72 + 64 * 68 + 64) * 4 + 2048 + 64)

extern "C" void kernel_launch(void* const* d_in, const int* in_sizes, int n_in,
                              void* d_out, int out_size) {
    (void)in_sizes; (void)n_in; (void)out_size;
    const float* X = (const float*)d_in[0];
    const float* W = (const float*)d_in[1];
    const void* mask = d_in[2];
    float* att = (float*)d_out;
    float* wts = (float*)d_out + (size_t)BATCH * NTOK * CHID;

    cudaFuncSetAttribute(attn_scores, cudaFuncAttributeMaxDynamicSharedMemorySize, ATT_SMEM);

    qkv_gemm<<<dim3(24, 32), 256, GEMM_SMEM>>>(X, W);
    attn_scores<<<dim3(32, HEADS, BATCH), 256, ATT_SMEM>>>(mask, att, wts);
    normalize_w<<<4096, 256>>>(wts);
}

// round 11
// speedup vs baseline: 1.3809x; 1.0267x over previous
#include <cuda_runtime.h>
#include <mma.h>
#include <math.h>

using namespace nvcuda;

#define HEADS 16
#define DIM 64
#define NTOK 2048
#define CHID 1024
#define BATCH 2
#define SCALE 0.125f

__device__ float g_qkv[3UL * BATCH * HEADS * NTOK * DIM];
__device__ float g_inv[(size_t)BATCH * HEADS * NTOK];

typedef wmma::fragment<wmma::matrix_a, 16, 16, 8, wmma::precision::tf32, wmma::row_major> AFrag;
typedef wmma::fragment<wmma::matrix_b, 16, 16, 8, wmma::precision::tf32, wmma::col_major> BFragCol;
typedef wmma::fragment<wmma::matrix_b, 16, 16, 8, wmma::precision::tf32, wmma::row_major> BFragRow;
typedef wmma::fragment<wmma::accumulator, 16, 16, 8, float> CFrag;

__device__ __forceinline__ float tf32r(float x) { return wmma::__float_to_tf32(x); }
__device__ __forceinline__ float4 tf4(float4 v) {
    v.x = tf32r(v.x); v.y = tf32r(v.y); v.z = tf32r(v.z); v.w = tf32r(v.w);
    return v;
}
__device__ __forceinline__ void cp16(void* s, const void* g) {
    unsigned sa = (unsigned)__cvta_generic_to_shared(s);
    asm volatile("cp.async.cg.shared.global [%0], [%1], 16;" :: "r"(sa), "l"(g));
}
#define CP_COMMIT() asm volatile("cp.async.commit_group;")
#define CP_WAIT(n) asm volatile("cp.async.wait_group %0;" :: "n"(n))

#define GLD 28   // gemm staging stride: gcd(28,32)=4 -> 2-way conflicts (24 was 4-way)

// ---------------- QKV projection GEMM (tf32, cp.async double-buffered) ----------------
__global__ __launch_bounds__(256, 2) void qkv_gemm(const float* __restrict__ X,
                                                   const float* __restrict__ Wt) {
    extern __shared__ float sm1[];
    float* As = sm1;                      // [2][128*GLD]
    float* Bs = sm1 + 2 * 128 * GLD;      // [2][128*GLD]
    float* Cs = sm1;                      // epilogue alias [128][72]

    int t = threadIdx.x;
    int bm = blockIdx.y, bn = blockIdx.x;
    int w = t >> 5;
    int wr = w >> 1, wc = w & 1;
    int lrow = t >> 1;
    int lq = (t & 1) * 8;

    const float* Ag = X + (size_t)(bm * 128 + lrow) * 1024 + lq;
    const float* Bg = Wt + (size_t)(bn * 128 + lrow) * 1024 + lq;

    CFrag acc[2][4];
#pragma unroll
    for (int i = 0; i < 2; i++)
#pragma unroll
        for (int j = 0; j < 4; j++) wmma::fill_fragment(acc[i][j], 0.f);

    // prefetch slab 0
    {
        float* ad = &As[lrow * GLD + lq];
        float* bd = &Bs[lrow * GLD + lq];
        cp16(ad, Ag); cp16(ad + 4, Ag + 4);
        cp16(bd, Bg); cp16(bd + 4, Bg + 4);
        CP_COMMIT();
    }

    int buf = 0;
    for (int k0 = 0; k0 < 1024; k0 += 16, buf ^= 1) {
        if (k0 + 16 < 1024) {
            float* ad = &As[(buf ^ 1) * (128 * GLD) + lrow * GLD + lq];
            float* bd = &Bs[(buf ^ 1) * (128 * GLD) + lrow * GLD + lq];
            cp16(ad, Ag + k0 + 16); cp16(ad + 4, Ag + k0 + 20);
            cp16(bd, Bg + k0 + 16); cp16(bd + 4, Bg + k0 + 20);
            CP_COMMIT();
            CP_WAIT(1);
        } else {
            CP_WAIT(0);
        }
        __syncthreads();
        float* A = As + buf * (128 * GLD);
        float* B = Bs + buf * (128 * GLD);
#pragma unroll
        for (int ks = 0; ks < 2; ks++) {
            AFrag af[2];
            BFragCol bf[4];
#pragma unroll
            for (int i = 0; i < 2; i++) {
                wmma::load_matrix_sync(af[i], &A[(wr * 32 + i * 16) * GLD + ks * 8], GLD);
#pragma unroll
                for (int e = 0; e < af[i].num_elements; e++) af[i].x[e] = tf32r(af[i].x[e]);
            }
#pragma unroll
            for (int j = 0; j < 4; j++) {
                wmma::load_matrix_sync(bf[j], &B[(wc * 64 + j * 16) * GLD + ks * 8], GLD);
#pragma unroll
                for (int e = 0; e < bf[j].num_elements; e++) bf[j].x[e] = tf32r(bf[j].x[e]);
            }
#pragma unroll
            for (int i = 0; i < 2; i++)
#pragma unroll
                for (int j = 0; j < 4; j++)
                    wmma::mma_sync(acc[i][j], af[i], bf[j], acc[i][j]);
        }
        __syncthreads();
    }

    // epilogue: round to tf32, scatter to g_qkv layout
#pragma unroll
    for (int hf = 0; hf < 2; hf++) {
        if (wc == hf) {
#pragma unroll
            for (int i = 0; i < 2; i++)
#pragma unroll
                for (int j = 0; j < 4; j++)
                    wmma::store_matrix_sync(&Cs[(wr * 32 + i * 16) * 72 + j * 16],
                                            acc[i][j], 72, wmma::mem_row_major);
        }
        __syncthreads();
        int colbase = bn * 128 + hf * 64;
        int qkv = colbase >> 10;
        int hh = (colbase >> 6) & 15;
#pragma unroll
        for (int i = 0; i < 8; i++) {
            int fi = t + (i << 8);
            int row = fi >> 4;
            int c4 = fi & 15;
            int m = bm * 128 + row;
            int b = m >> 11, n = m & 2047;
            float4 v = tf4(*(const float4*)&Cs[row * 72 + c4 * 4]);
            float* dst = g_qkv + ((((size_t)qkv * BATCH + b) * HEADS + hh) * NTOK + n) * DIM + c4 * 4;
            *(float4*)dst = v;
        }
        __syncthreads();
    }
}

// ---------------- attention: 64-row Q tiles, 64-col chunks (R9, unchanged) ----------------
__global__ __launch_bounds__(256, 2) void attn_scores(const void* __restrict__ mask_raw,
                                                      float* __restrict__ att_out,
                                                      float* __restrict__ w_out) {
    extern __shared__ float sm[];
    float* qs = sm;                     // [64][72]
    float* kb = qs + 64 * 72;           // 2 x [64][72]
    float* sc = kb + 2 * 64 * 72;       // [64][68]
    float* rowsum = sc + 64 * 68;       // [64]
    unsigned char* mj = (unsigned char*)(rowsum + 64);  // 2048
    unsigned char* mr = mj + 2048;      // 64

    __shared__ int s_is32;

    int t = threadIdx.x;
    int w = t >> 5;
    int wr = w >> 1;
    int wh = w & 1;
    int b = blockIdx.z, h = blockIdx.y;
    int row0 = blockIdx.x << 6;

    const float* Qg = g_qkv + (((size_t)(0 * BATCH + b) * HEADS + h) * NTOK + row0) * DIM;
    const float* Kg = g_qkv + (((size_t)(1 * BATCH + b) * HEADS + h) * NTOK) * DIM;
    const float* Vg = g_qkv + (((size_t)(2 * BATCH + b) * HEADS + h) * NTOK) * DIM;
    float* Wt = w_out + ((size_t)(b * HEADS + h) * NTOK + row0) * NTOK;

#pragma unroll
    for (int i = 0; i < 4; i++) {
        int fi = t + (i << 8);
        int r = fi >> 4;
        int d4 = (fi & 15) << 2;
        cp16(&qs[r * 72 + d4], Qg + (size_t)r * DIM + d4);
        cp16(&kb[r * 72 + d4], Kg + (size_t)r * DIM + d4);
    }
    CP_COMMIT();

    if (t == 0) {
        const unsigned int* mw = (const unsigned int*)mask_raw;
        int is32 = 1;
        for (int i = 0; i < 64; i++)
            if (mw[i] > 1u) { is32 = 0; break; }
        s_is32 = is32;
    }
    __syncthreads();
    {
        const int is32 = s_is32;
        const int* m32 = (const int*)mask_raw;
        const unsigned char* m8 = (const unsigned char*)mask_raw;
#pragma unroll
        for (int i = 0; i < 8; i++) {
            int j = t + (i << 8);
            mj[j] = is32 ? (unsigned char)(m32[(size_t)b * NTOK + j] != 0)
                         : m8[(size_t)b * NTOK + j];
        }
        if (t < 64) {
            int idx = b * NTOK + row0 + t;
            int mv = is32 ? (m32[idx] != 0) : (m8[idx] != 0);
            mr[t] = (unsigned char)mv;
            rowsum[t] = 0.f;
        }
    }
    __syncthreads();

    // ---------- Phase A ----------
    {
        AFrag aq[8];

        for (int cb = 0; cb < 32; cb++) {
            if (cb + 1 < 32) {
                float* dst = kb + ((cb + 1) & 1) * (64 * 72);
#pragma unroll
                for (int i = 0; i < 4; i++) {
                    int fi = t + (i << 8);
                    int r = fi >> 4;
                    int d4 = (fi & 15) << 2;
                    cp16(&dst[r * 72 + d4], Kg + (size_t)((cb + 1) * 64 + r) * DIM + d4);
                }
                CP_COMMIT();
                CP_WAIT(1);
            } else {
                CP_WAIT(0);
            }
            __syncthreads();
            float* buf = kb + (cb & 1) * (64 * 72);

            if (cb == 0) {
#pragma unroll
                for (int k = 0; k < 8; k++)
                    wmma::load_matrix_sync(aq[k], &qs[(wr * 16) * 72 + k * 8], 72);
            }

#pragma unroll
            for (int c = 0; c < 2; c++) {
                CFrag acc;
                wmma::fill_fragment(acc, 0.f);
#pragma unroll
                for (int k = 0; k < 8; k++) {
                    BFragCol bf;
                    wmma::load_matrix_sync(bf, &buf[(wh * 32 + c * 16) * 72 + k * 8], 72);
                    wmma::mma_sync(acc, aq[k], bf, acc);
                }
                wmma::store_matrix_sync(&sc[(wr * 16) * 68 + wh * 32 + c * 16], acc, 68,
                                        wmma::mem_row_major);
            }
            __syncthreads();

            {
                int r = t >> 2;
                int c0 = (t & 3) << 4;
                bool rm = mr[r] != 0;
                const unsigned char* mjc = mj + cb * 64 + c0;
                float* p = &sc[r * 68 + c0];
                float lsum = 0.f;
#pragma unroll
                for (int j4 = 0; j4 < 4; j4++) {
                    float4 v = *(const float4*)(p + j4 * 4);
                    float4 e;
                    e.x = rm ? 1.f : (mjc[j4 * 4 + 0] ? 0.f : __expf(v.x * SCALE));
                    e.y = rm ? 1.f : (mjc[j4 * 4 + 1] ? 0.f : __expf(v.y * SCALE));
                    e.z = rm ? 1.f : (mjc[j4 * 4 + 2] ? 0.f : __expf(v.z * SCALE));
                    e.w = rm ? 1.f : (mjc[j4 * 4 + 3] ? 0.f : __expf(v.w * SCALE));
                    *(float4*)(p + j4 * 4) = e;
                    lsum += e.x + e.y + e.z + e.w;
                }
                lsum += __shfl_xor_sync(0xffffffffu, lsum, 1);
                lsum += __shfl_xor_sync(0xffffffffu, lsum, 2);
                if ((t & 3) == 0) rowsum[r] += lsum;
            }
            __syncthreads();

#pragma unroll
            for (int i = 0; i < 4; i++) {
                int fi = t + (i << 8);
                int r = fi >> 4;
                int c4 = (fi & 15) << 2;
                *(float4*)(Wt + (size_t)r * NTOK + cb * 64 + c4) = *(const float4*)&sc[r * 68 + c4];
            }
        }
    }

    __syncthreads();
    if (t < 64) {
        float inv = 1.f / rowsum[t];
        rowsum[t] = inv;
        g_inv[((size_t)(b * HEADS + h) * NTOK) + row0 + t] = inv;
    }
    __syncthreads();

    // ---------- Phase B ----------
    {
        CFrag acc[2];
#pragma unroll
        for (int dt = 0; dt < 2; dt++) wmma::fill_fragment(acc[dt], 0.f);

#pragma unroll
        for (int i = 0; i < 4; i++) {
            int fi = t + (i << 8);
            int r = fi >> 4;
            int d4 = (fi & 15) << 2;
            cp16(&kb[r * 72 + d4], Vg + (size_t)r * DIM + d4);
        }
        CP_COMMIT();

        for (int cb = 0; cb < 32; cb++) {
#pragma unroll
            for (int i = 0; i < 4; i++) {
                int fi = t + (i << 8);
                int r = fi >> 4;
                int c4 = (fi & 15) << 2;
                float4 v = *(const float4*)(Wt + (size_t)r * NTOK + cb * 64 + c4);
                *(float4*)&sc[r * 68 + c4] = tf4(v);
            }
            if (cb + 1 < 32) {
                float* dst = kb + ((cb + 1) & 1) * (64 * 72);
#pragma unroll
                for (int i = 0; i < 4; i++) {
                    int fi = t + (i << 8);
                    int r = fi >> 4;
                    int d4 = (fi & 15) << 2;
                    cp16(&dst[r * 72 + d4], Vg + (size_t)((cb + 1) * 64 + r) * DIM + d4);
                }
                CP_COMMIT();
                CP_WAIT(1);
            } else {
                CP_WAIT(0);
            }
            __syncthreads();
            float* buf = kb + (cb & 1) * (64 * 72);

#pragma unroll
            for (int k = 0; k < 8; k++) {
                AFrag ae;
                wmma::load_matrix_sync(ae, &sc[(wr * 16) * 68 + k * 8], 68);
#pragma unroll
                for (int dt = 0; dt < 2; dt++) {
                    BFragRow bv;
                    wmma::load_matrix_sync(bv, &buf[(k * 8) * 72 + wh * 32 + dt * 16], 72);
                    wmma::mma_sync(acc[dt], ae, bv, acc[dt]);
                }
            }
            __syncthreads();
        }

#pragma unroll
        for (int dt = 0; dt < 2; dt++)
            wmma::store_matrix_sync(&sc[(wr * 16) * 68 + wh * 32 + dt * 16], acc[dt], 68,
                                    wmma::mem_row_major);
        __syncthreads();
        {
            int r = t >> 2;
            int d0 = (t & 3) << 4;
            float inv = rowsum[r];
            float* dst = att_out + ((size_t)b * NTOK + row0 + r) * CHID + h * DIM + d0;
#pragma unroll
            for (int j4 = 0; j4 < 4; j4++) {
                float4 v = *(const float4*)&sc[r * 68 + d0 + j4 * 4];
                v.x *= inv; v.y *= inv; v.z *= inv; v.w *= inv;
                *(float4*)(dst + j4 * 4) = v;
            }
        }
    }
}

// ---------------- normalize weights (full-chip parallel) ----------------
__global__ __launch_bounds__(256) void normalize_w(float* __restrict__ w_out) {
    size_t nf4 = (size_t)BATCH * HEADS * NTOK * NTOK / 4;
    size_t stride = (size_t)gridDim.x * blockDim.x;
    for (size_t i = (size_t)blockIdx.x * blockDim.x + threadIdx.x; i < nf4; i += stride) {
        size_t fidx = i << 2;
        float inv = __ldg(&g_inv[fidx >> 11]);
        float4 v = *(float4*)(w_out + fidx);
        v.x *= inv; v.y *= inv; v.z *= inv; v.w *= inv;
        *(float4*)(w_out + fidx) = v;
    }
}

#define GEMM_SMEM (2 * 2 * 128 * GLD * 4)
#define ATT_SMEM ((64 * 72 + 2 * 64 * 72 + 64 * 68 + 64) * 4 + 2048 + 64)

extern "C" void kernel_launch(void* const* d_in, const int* in_sizes, int n_in,
                              void* d_out, int out_size) {
    (void)in_sizes; (void)n_in; (void)out_size;
    const float* X = (const float*)d_in[0];
    const float* W = (const float*)d_in[1];
    const void* mask = d_in[2];
    float* att = (float*)d_out;
    float* wts = (float*)d_out + (size_t)BATCH * NTOK * CHID;

    // GEMM_SMEM = 57344 > 48KB default -> attribute REQUIRED (R10 failed without it)
    cudaFuncSetAttribute(qkv_gemm, cudaFuncAttributeMaxDynamicSharedMemorySize, GEMM_SMEM);
    cudaFuncSetAttribute(attn_scores, cudaFuncAttributeMaxDynamicSharedMemorySize, ATT_SMEM);

    qkv_gemm<<<dim3(24, 32), 256, GEMM_SMEM>>>(X, W);
    attn_scores<<<dim3(32, HEADS, BATCH), 256, ATT_SMEM>>>(mask, att, wts);
    normalize_w<<<4096, 256>>>(wts);
}

// round 12
// speedup vs baseline: 1.4333x; 1.0379x over previous
#include <cuda_runtime.h>
#include <mma.h>
#include <math.h>

using namespace nvcuda;

#define HEADS 16
#define DIM 64
#define NTOK 2048
#define CHID 1024
#define BATCH 2
#define SCALE 0.125f

__device__ float g_qkv[3UL * BATCH * HEADS * NTOK * DIM];
__device__ float g_inv[(size_t)BATCH * HEADS * NTOK];

typedef wmma::fragment<wmma::matrix_a, 16, 16, 8, wmma::precision::tf32, wmma::row_major> AFrag;
typedef wmma::fragment<wmma::matrix_b, 16, 16, 8, wmma::precision::tf32, wmma::col_major> BFragCol;
typedef wmma::fragment<wmma::matrix_b, 16, 16, 8, wmma::precision::tf32, wmma::row_major> BFragRow;
typedef wmma::fragment<wmma::accumulator, 16, 16, 8, float> CFrag;

__device__ __forceinline__ float tf32r(float x) { return wmma::__float_to_tf32(x); }
__device__ __forceinline__ float4 tf4(float4 v) {
    v.x = tf32r(v.x); v.y = tf32r(v.y); v.z = tf32r(v.z); v.w = tf32r(v.w);
    return v;
}
__device__ __forceinline__ void cp16(void* s, const void* g) {
    unsigned sa = (unsigned)__cvta_generic_to_shared(s);
    asm volatile("cp.async.cg.shared.global [%0], [%1], 16;" :: "r"(sa), "l"(g));
}
#define CP_COMMIT() asm volatile("cp.async.commit_group;")
#define CP_WAIT(n) asm volatile("cp.async.wait_group %0;" :: "n"(n))

#define GLD 28

// ---------------- QKV projection GEMM (R11, unchanged: 405us measured) ----------------
__global__ __launch_bounds__(256, 2) void qkv_gemm(const float* __restrict__ X,
                                                   const float* __restrict__ Wt) {
    extern __shared__ float sm1[];
    float* As = sm1;
    float* Bs = sm1 + 2 * 128 * GLD;
    float* Cs = sm1;

    int t = threadIdx.x;
    int bm = blockIdx.y, bn = blockIdx.x;
    int w = t >> 5;
    int wr = w >> 1, wc = w & 1;
    int lrow = t >> 1;
    int lq = (t & 1) * 8;

    const float* Ag = X + (size_t)(bm * 128 + lrow) * 1024 + lq;
    const float* Bg = Wt + (size_t)(bn * 128 + lrow) * 1024 + lq;

    CFrag acc[2][4];
#pragma unroll
    for (int i = 0; i < 2; i++)
#pragma unroll
        for (int j = 0; j < 4; j++) wmma::fill_fragment(acc[i][j], 0.f);

    {
        float* ad = &As[lrow * GLD + lq];
        float* bd = &Bs[lrow * GLD + lq];
        cp16(ad, Ag); cp16(ad + 4, Ag + 4);
        cp16(bd, Bg); cp16(bd + 4, Bg + 4);
        CP_COMMIT();
    }

    int buf = 0;
    for (int k0 = 0; k0 < 1024; k0 += 16, buf ^= 1) {
        if (k0 + 16 < 1024) {
            float* ad = &As[(buf ^ 1) * (128 * GLD) + lrow * GLD + lq];
            float* bd = &Bs[(buf ^ 1) * (128 * GLD) + lrow * GLD + lq];
            cp16(ad, Ag + k0 + 16); cp16(ad + 4, Ag + k0 + 20);
            cp16(bd, Bg + k0 + 16); cp16(bd + 4, Bg + k0 + 20);
            CP_COMMIT();
            CP_WAIT(1);
        } else {
            CP_WAIT(0);
        }
        __syncthreads();
        float* A = As + buf * (128 * GLD);
        float* B = Bs + buf * (128 * GLD);
#pragma unroll
        for (int ks = 0; ks < 2; ks++) {
            AFrag af[2];
            BFragCol bf[4];
#pragma unroll
            for (int i = 0; i < 2; i++) {
                wmma::load_matrix_sync(af[i], &A[(wr * 32 + i * 16) * GLD + ks * 8], GLD);
#pragma unroll
                for (int e = 0; e < af[i].num_elements; e++) af[i].x[e] = tf32r(af[i].x[e]);
            }
#pragma unroll
            for (int j = 0; j < 4; j++) {
                wmma::load_matrix_sync(bf[j], &B[(wc * 64 + j * 16) * GLD + ks * 8], GLD);
#pragma unroll
                for (int e = 0; e < bf[j].num_elements; e++) bf[j].x[e] = tf32r(bf[j].x[e]);
            }
#pragma unroll
            for (int i = 0; i < 2; i++)
#pragma unroll
                for (int j = 0; j < 4; j++)
                    wmma::mma_sync(acc[i][j], af[i], bf[j], acc[i][j]);
        }
        __syncthreads();
    }

#pragma unroll
    for (int hf = 0; hf < 2; hf++) {
        if (wc == hf) {
#pragma unroll
            for (int i = 0; i < 2; i++)
#pragma unroll
                for (int j = 0; j < 4; j++)
                    wmma::store_matrix_sync(&Cs[(wr * 32 + i * 16) * 72 + j * 16],
                                            acc[i][j], 72, wmma::mem_row_major);
        }
        __syncthreads();
        int colbase = bn * 128 + hf * 64;
        int qkv = colbase >> 10;
        int hh = (colbase >> 6) & 15;
#pragma unroll
        for (int i = 0; i < 8; i++) {
            int fi = t + (i << 8);
            int row = fi >> 4;
            int c4 = fi & 15;
            int m = bm * 128 + row;
            int b = m >> 11, n = m & 2047;
            float4 v = tf4(*(const float4*)&Cs[row * 72 + c4 * 4]);
            float* dst = g_qkv + ((((size_t)qkv * BATCH + b) * HEADS + hh) * NTOK + n) * DIM + c4 * 4;
            *(float4*)dst = v;
        }
        __syncthreads();
    }
}

// ---------------- fused attention: single pass, K+V co-streamed ----------------
// Per 64-col chunk: S = Q K^T -> e = masked exp -> e to w_out (unnormalized)
// + AV += e @ V (e straight from smem). Epilogue: att = AV / rowsum.
__global__ __launch_bounds__(256, 2) void attn_fused(const void* __restrict__ mask_raw,
                                                     float* __restrict__ att_out,
                                                     float* __restrict__ w_out) {
    extern __shared__ float sm[];
    float* qs = sm;                     // [64][72]
    float* kv = qs + 64 * 72;           // 2 x [128][72]  (rows 0-63 K, 64-127 V)
    float* sc = kv + 2 * 128 * 72;      // [64][68]
    float* rowsum = sc + 64 * 68;       // [64]
    unsigned char* mj = (unsigned char*)(rowsum + 64);  // 2048
    unsigned char* mr = mj + 2048;      // 64

    __shared__ int s_is32;

    int t = threadIdx.x;
    int w = t >> 5;
    int wr = w >> 1;      // 16-row group
    int wh = w & 1;       // 32-col half
    int b = blockIdx.z, h = blockIdx.y;
    int row0 = blockIdx.x << 6;

    const float* Qg = g_qkv + (((size_t)(0 * BATCH + b) * HEADS + h) * NTOK + row0) * DIM;
    const float* Kg = g_qkv + (((size_t)(1 * BATCH + b) * HEADS + h) * NTOK) * DIM;
    const float* Vg = g_qkv + (((size_t)(2 * BATCH + b) * HEADS + h) * NTOK) * DIM;
    float* Wt = w_out + ((size_t)(b * HEADS + h) * NTOK + row0) * NTOK;

    // stage Q + chunk 0 (K rows 0-63, V rows 64-127)
#pragma unroll
    for (int i = 0; i < 4; i++) {
        int fi = t + (i << 8);
        int r = fi >> 4;
        int d4 = (fi & 15) << 2;
        cp16(&qs[r * 72 + d4], Qg + (size_t)r * DIM + d4);
    }
#pragma unroll
    for (int i = 0; i < 8; i++) {
        int fi = t + (i << 8);
        int r = fi >> 4;             // 0..127
        int d4 = (fi & 15) << 2;
        const float* src = (r < 64) ? (Kg + (size_t)r * DIM + d4)
                                    : (Vg + (size_t)(r - 64) * DIM + d4);
        cp16(&kv[r * 72 + d4], src);
    }
    CP_COMMIT();

    if (t == 0) {
        const unsigned int* mw = (const unsigned int*)mask_raw;
        int is32 = 1;
        for (int i = 0; i < 64; i++)
            if (mw[i] > 1u) { is32 = 0; break; }
        s_is32 = is32;
    }
    __syncthreads();
    {
        const int is32 = s_is32;
        const int* m32 = (const int*)mask_raw;
        const unsigned char* m8 = (const unsigned char*)mask_raw;
#pragma unroll
        for (int i = 0; i < 8; i++) {
            int j = t + (i << 8);
            mj[j] = is32 ? (unsigned char)(m32[(size_t)b * NTOK + j] != 0)
                         : m8[(size_t)b * NTOK + j];
        }
        if (t < 64) {
            int idx = b * NTOK + row0 + t;
            int mv = is32 ? (m32[idx] != 0) : (m8[idx] != 0);
            mr[t] = (unsigned char)mv;
            rowsum[t] = 0.f;
        }
    }
    __syncthreads();

    AFrag aq[8];
    CFrag av[2];
#pragma unroll
    for (int dt = 0; dt < 2; dt++) wmma::fill_fragment(av[dt], 0.f);

    for (int cb = 0; cb < 32; cb++) {
        // prefetch next chunk K+V
        if (cb + 1 < 32) {
            float* dst = kv + ((cb + 1) & 1) * (128 * 72);
#pragma unroll
            for (int i = 0; i < 8; i++) {
                int fi = t + (i << 8);
                int r = fi >> 4;
                int d4 = (fi & 15) << 2;
                const float* src = (r < 64) ? (Kg + (size_t)((cb + 1) * 64 + r) * DIM + d4)
                                            : (Vg + (size_t)((cb + 1) * 64 + (r - 64)) * DIM + d4);
                cp16(&dst[r * 72 + d4], src);
            }
            CP_COMMIT();
            CP_WAIT(1);
        } else {
            CP_WAIT(0);
        }
        __syncthreads();
        float* buf = kv + (cb & 1) * (128 * 72);

        if (cb == 0) {
#pragma unroll
            for (int k = 0; k < 8; k++)
                wmma::load_matrix_sync(aq[k], &qs[(wr * 16) * 72 + k * 8], 72);
        }

        // S = Q K^T : warp does 16 rows x 32 cols
#pragma unroll
        for (int c = 0; c < 2; c++) {
            CFrag acc;
            wmma::fill_fragment(acc, 0.f);
#pragma unroll
            for (int k = 0; k < 8; k++) {
                BFragCol bf;
                wmma::load_matrix_sync(bf, &buf[(wh * 32 + c * 16) * 72 + k * 8], 72);
                wmma::mma_sync(acc, aq[k], bf, acc);
            }
            wmma::store_matrix_sync(&sc[(wr * 16) * 68 + wh * 32 + c * 16], acc, 68,
                                    wmma::mem_row_major);
        }
        __syncthreads();

        // e = masked exp; rowsum accumulate (4 threads/row)
        {
            int r = t >> 2;
            int c0 = (t & 3) << 4;
            bool rm = mr[r] != 0;
            const unsigned char* mjc = mj + cb * 64 + c0;
            float* p = &sc[r * 68 + c0];
            float lsum = 0.f;
#pragma unroll
            for (int j4 = 0; j4 < 4; j4++) {
                float4 v = *(const float4*)(p + j4 * 4);
                float4 e;
                e.x = rm ? 1.f : (mjc[j4 * 4 + 0] ? 0.f : __expf(v.x * SCALE));
                e.y = rm ? 1.f : (mjc[j4 * 4 + 1] ? 0.f : __expf(v.y * SCALE));
                e.z = rm ? 1.f : (mjc[j4 * 4 + 2] ? 0.f : __expf(v.z * SCALE));
                e.w = rm ? 1.f : (mjc[j4 * 4 + 3] ? 0.f : __expf(v.w * SCALE));
                *(float4*)(p + j4 * 4) = e;
                lsum += e.x + e.y + e.z + e.w;
            }
            lsum += __shfl_xor_sync(0xffffffffu, lsum, 1);
            lsum += __shfl_xor_sync(0xffffffffu, lsum, 2);
            if ((t & 3) == 0) rowsum[r] += lsum;
        }
        __syncthreads();

        // store unnormalized e chunk to w_out
#pragma unroll
        for (int i = 0; i < 4; i++) {
            int fi = t + (i << 8);
            int r = fi >> 4;
            int c4 = (fi & 15) << 2;
            *(float4*)(Wt + (size_t)r * NTOK + cb * 64 + c4) = *(const float4*)&sc[r * 68 + c4];
        }

        // AV += e @ V  (e from sc, tf32-rounded in fragment; V rows 64-127 of buf)
#pragma unroll
        for (int k = 0; k < 8; k++) {
            AFrag ae;
            wmma::load_matrix_sync(ae, &sc[(wr * 16) * 68 + k * 8], 68);
#pragma unroll
            for (int e = 0; e < ae.num_elements; e++) ae.x[e] = tf32r(ae.x[e]);
#pragma unroll
            for (int dt = 0; dt < 2; dt++) {
                BFragRow bv;
                wmma::load_matrix_sync(bv, &buf[(64 + k * 8) * 72 + wh * 32 + dt * 16], 72);
                wmma::mma_sync(av[dt], ae, bv, av[dt]);
            }
        }
        // guard: next iter's cp.async targets the buffer we just read
        __syncthreads();
    }

    if (t < 64) {
        float inv = 1.f / rowsum[t];
        rowsum[t] = inv;
        g_inv[((size_t)(b * HEADS + h) * NTOK) + row0 + t] = inv;
    }

    // epilogue: stage AV, scale by inv, write att
#pragma unroll
    for (int dt = 0; dt < 2; dt++)
        wmma::store_matrix_sync(&sc[(wr * 16) * 68 + wh * 32 + dt * 16], av[dt], 68,
                                wmma::mem_row_major);
    __syncthreads();
    {
        int r = t >> 2;
        int d0 = (t & 3) << 4;
        float inv = rowsum[r];
        float* dst = att_out + ((size_t)b * NTOK + row0 + r) * CHID + h * DIM + d0;
#pragma unroll
        for (int j4 = 0; j4 < 4; j4++) {
            float4 v = *(const float4*)&sc[r * 68 + d0 + j4 * 4];
            v.x *= inv; v.y *= inv; v.z *= inv; v.w *= inv;
            *(float4*)(dst + j4 * 4) = v;
        }
    }
}

// ---------------- normalize weights (full-chip parallel) ----------------
__global__ __launch_bounds__(256) void normalize_w(float* __restrict__ w_out) {
    size_t nf4 = (size_t)BATCH * HEADS * NTOK * NTOK / 4;
    size_t stride = (size_t)gridDim.x * blockDim.x;
    for (size_t i = (size_t)blockIdx.x * blockDim.x + threadIdx.x; i < nf4; i += stride) {
        size_t fidx = i << 2;
        float inv = __ldg(&g_inv[fidx >> 11]);
        float4 v = *(float4*)(w_out + fidx);
        v.x *= inv; v.y *= inv; v.z *= inv; v.w *= inv;
        *(float4*)(w_out + fidx) = v;
    }
}

#define GEMM_SMEM (2 * 2 * 128 * GLD * 4)
#define ATT_SMEM ((64 * 72 + 2 * 128 * 72 + 64 * 68 + 64) * 4 + 2048 + 64)

extern "C" void kernel_launch(void* const* d_in, const int* in_sizes, int n_in,
                              void* d_out, int out_size) {
    (void)in_sizes; (void)n_in; (void)out_size;
    const float* X = (const float*)d_in[0];
    const float* W = (const float*)d_in[1];
    const void* mask = d_in[2];
    float* att = (float*)d_out;
    float* wts = (float*)d_out + (size_t)BATCH * NTOK * CHID;

    cudaFuncSetAttribute(qkv_gemm, cudaFuncAttributeMaxDynamicSharedMemorySize, GEMM_SMEM);
    cudaFuncSetAttribute(attn_fused, cudaFuncAttributeMaxDynamicSharedMemorySize, ATT_SMEM);

    qkv_gemm<<<dim3(24, 32), 256, GEMM_SMEM>>>(X, W);
    attn_fused<<<dim3(32, HEADS, BATCH), 256, ATT_SMEM>>>(mask, att, wts);
    normalize_w<<<4096, 256>>>(wts);
}